// round 10
// baseline (speedup 1.0000x reference)
#include <cuda_runtime.h>
#include <cstdint>

// ---------------------------------------------------------------------------
// Sequential LSTM rollout, N=10000 steps, H=1024.
// 128 persistent CTAs x 256 threads. WARP-AUTONOMOUS steps: warp w of CTA b
// owns output h[8b+w] and computes ALL FOUR of its gate rows completely
// (rows g*1024+8b+w, g=0..3). No __syncthreads, no cross-warp reduce in the
// steady state.
//   - weights: 4 rows x 16 f32x2 pairs/lane in registers (=64 ull, as R7)
//   - h_{t-1}: 8x ldcg ulonglong2 per lane straight into registers
//   - row sums: 5-level butterfly shfl (all lanes get all 4 sums)
//   - activations: lanes 0-3 in parallel, lane0 updates c / publishes h
// CTA completion: monotonic smem atom.acq_rel counter; 8th warp runs the
// R7-proven tail (__threadfence + red.global.add g_cnt).
// Observe: R7-proven single poller (warp0 lane0) on g_cnt + smem relay.
// Safety: global counter needs ALL CTAs => 1-step skew bound; smem counter
// orders all warps' h stores before CTA publish => parity buffers safe.
// ---------------------------------------------------------------------------

#define HDIM  1024
#define NCTA  128
#define TPB   256
#define NWARP 8

typedef unsigned long long ull;

__device__ __align__(16) float g_hbuf[2][HDIM];
__device__ unsigned            g_cnt;

__device__ __forceinline__ ull ffma2(ull a, ull b, ull c) {
    ull d;
    asm("fma.rn.f32x2 %0, %1, %2, %3;" : "=l"(d) : "l"(a), "l"(b), "l"(c));
    return d;
}
__device__ __forceinline__ float pairsum(ull a) {
    float lo = __uint_as_float((unsigned)(a & 0xffffffffull));
    float hi = __uint_as_float((unsigned)(a >> 32));
    return lo + hi;
}
__device__ __forceinline__ float sigf(float x) {
    return 1.0f / (1.0f + __expf(-x));
}
__device__ __forceinline__ float tanh_fast(float x) {
    x = fminf(15.0f, fmaxf(-15.0f, x));
    float e = __expf(-2.0f * x);
    return (1.0f - e) / (1.0f + e);
}
__device__ __forceinline__ unsigned ld_acq_gpu(const unsigned* p) {
    unsigned v;
    asm volatile("ld.acquire.gpu.u32 %0, [%1];" : "=r"(v) : "l"(p));
    return v;
}
__device__ __forceinline__ uint32_t smem_u32(const void* p) {
    uint32_t a;
    asm("{ .reg .u64 t; cvta.to.shared.u64 t, %1; cvt.u32.u64 %0, t; }"
        : "=r"(a) : "l"(p));
    return a;
}

__global__ void lstm_init_kernel() {
    if (threadIdx.x == 0) g_cnt = 0u;
}

__global__ void __launch_bounds__(TPB) lstm_kernel(
    const float* __restrict__ x,      // [1024]
    const float* __restrict__ W_ih,   // [4096,1024] row-major
    const float* __restrict__ W_hh,   // [4096,1024] row-major
    const float* __restrict__ b_ih,   // [4096]
    const float* __restrict__ b_hh,   // [4096]
    float* __restrict__ out,          // [N,1024]
    int N)
{
    __shared__ unsigned sh_step;           // monotonic step relay
    __shared__ unsigned sh_cnt;            // monotonic warp-completion counter

    const int tid = threadIdx.x;
    const int w   = tid >> 5;              // warp 0..7 -> owns output cta*8+w
    const int l   = tid & 31;
    const int cta = blockIdx.x;
    const int outIdx = cta * 8 + w;
    const uint32_t stepAddr = smem_u32(&sh_step);
    const uint32_t cntAddr  = smem_u32(&sh_cnt);

    if (tid == 0) { sh_step = 0u; sh_cnt = 0u; }
    __syncthreads();

    // rows for this warp's 4 gates (i,f,g,o)
    // lane l handles f32x2 pairs {2*(l+32j), 2*(l+32j)+1 : j=0..7} of each row
    // (float4-granular, coalesced across lanes)

    // ---- prologue: xg[r] = x @ W_ih[row_r] + b_ih + b_hh (warp-local) ----
    float xg0, xg1, xg2, xg3;
    {
        ull xa[2 * 8];                       // x pairs per j
        #pragma unroll
        for (int j = 0; j < 8; ++j) {
            ulonglong2 v = *((const ulonglong2*)x + (l + 32 * j));
            xa[2 * j] = v.x; xa[2 * j + 1] = v.y;
        }
        float s[4];
        #pragma unroll
        for (int r = 0; r < 4; ++r) {
            const ull* wp = (const ull*)W_ih + (size_t)(r * HDIM + outIdx) * (HDIM / 2);
            ull a0 = 0, a1 = 0;
            #pragma unroll
            for (int j = 0; j < 8; ++j) {
                a0 = ffma2(__ldg(wp + 2 * (l + 32 * j)),     xa[2 * j],     a0);
                a1 = ffma2(__ldg(wp + 2 * (l + 32 * j) + 1), xa[2 * j + 1], a1);
            }
            s[r] = pairsum(a0) + pairsum(a1);
        }
        #pragma unroll
        for (int off = 16; off >= 1; off >>= 1) {
            #pragma unroll
            for (int r = 0; r < 4; ++r)
                s[r] += __shfl_xor_sync(0xffffffffu, s[r], off);
        }
        xg0 = s[0] + b_ih[0 * HDIM + outIdx] + b_hh[0 * HDIM + outIdx];
        xg1 = s[1] + b_ih[1 * HDIM + outIdx] + b_hh[1 * HDIM + outIdx];
        xg2 = s[2] + b_ih[2 * HDIM + outIdx] + b_hh[2 * HDIM + outIdx];
        xg3 = s[3] + b_ih[3 * HDIM + outIdx] + b_hh[3 * HDIM + outIdx];
    }

    // ---- preload W_hh: 4 rows x 16 pairs per lane ----
    ull wreg[4][16];
    #pragma unroll
    for (int r = 0; r < 4; ++r) {
        const ull* wp = (const ull*)W_hh + (size_t)(r * HDIM + outIdx) * (HDIM / 2);
        #pragma unroll
        for (int j = 0; j < 8; ++j) {
            wreg[r][2 * j]     = wp[2 * (l + 32 * j)];
            wreg[r][2 * j + 1] = wp[2 * (l + 32 * j) + 1];
        }
    }

    // this lane's selected xg (for the parallel activation stage)
    const float xg_own = (l & 2) ? ((l & 1) ? xg3 : xg2)
                                 : ((l & 1) ? xg1 : xg0);

    // ---- recurrence: barrier-free, warp-autonomous ----
    float c = 0.f;
    unsigned target = 0u;                   // = 128*t

    for (int t = 0; t < N; ++t) {
        float s0 = 0.f, s1 = 0.f, s2 = 0.f, s3 = 0.f;
        if (t > 0) {
            const int p = (t - 1) & 1;
            const unsigned tt = (unsigned)t;

            if (w == 0) {
                if (l == 0) {
                    while ((int)(ld_acq_gpu(&g_cnt) - target) < 0) { }
                    asm volatile("st.release.cta.shared.u32 [%0], %1;"
                                 :: "r"(stepAddr), "r"(tt) : "memory");
                }
                __syncwarp();
            } else {
                unsigned v;
                do {
                    asm volatile("ld.acquire.cta.shared.u32 %0, [%1];"
                                 : "=r"(v) : "r"(stepAddr) : "memory");
                } while ((int)(v - tt) < 0);
            }

            // full h straight into registers + FMA against 4 rows
            ull a0 = 0, a1 = 0, a2 = 0, a3 = 0;
            const ulonglong2* hp = (const ulonglong2*)g_hbuf[p];
            #pragma unroll
            for (int j = 0; j < 8; ++j) {
                ulonglong2 hv = __ldcg(hp + (l + 32 * j));
                a0 = ffma2(wreg[0][2 * j], hv.x, a0);
                a0 = ffma2(wreg[0][2 * j + 1], hv.y, a0);
                a1 = ffma2(wreg[1][2 * j], hv.x, a1);
                a1 = ffma2(wreg[1][2 * j + 1], hv.y, a1);
                a2 = ffma2(wreg[2][2 * j], hv.x, a2);
                a2 = ffma2(wreg[2][2 * j + 1], hv.y, a2);
                a3 = ffma2(wreg[3][2 * j], hv.x, a3);
                a3 = ffma2(wreg[3][2 * j + 1], hv.y, a3);
            }
            s0 = pairsum(a0); s1 = pairsum(a1);
            s2 = pairsum(a2); s3 = pairsum(a3);
            // butterfly: every lane ends with all 4 complete sums
            #pragma unroll
            for (int off = 16; off >= 1; off >>= 1) {
                s0 += __shfl_xor_sync(0xffffffffu, s0, off);
                s1 += __shfl_xor_sync(0xffffffffu, s1, off);
                s2 += __shfl_xor_sync(0xffffffffu, s2, off);
                s3 += __shfl_xor_sync(0xffffffffu, s3, off);
            }
        }

        // parallel activations: lane r (r=0..3) activates gate r
        float val = xg_own + ((l & 2) ? ((l & 1) ? s3 : s2)
                                      : ((l & 1) ? s1 : s0));
        float act = ((l & 3) == 2) ? tanh_fast(val) : sigf(val);
        float a_i = __shfl_sync(0xffffffffu, act, 0);
        float a_f = __shfl_sync(0xffffffffu, act, 1);
        float a_g = __shfl_sync(0xffffffffu, act, 2);
        float a_o = __shfl_sync(0xffffffffu, act, 3);

        if (l == 0) {
            c = a_f * c + a_i * a_g;
            float hn = a_o * tanh_fast(c);
            __stcg(&g_hbuf[t & 1][outIdx], hn);
            // CTA-completion aggregation (monotonic, acq_rel chains warps)
            unsigned old;
            asm volatile("atom.acq_rel.cta.shared.add.u32 %0, [%1], %2;"
                         : "=r"(old) : "r"(cntAddr), "r"(1u) : "memory");
            if (old == (unsigned)(8 * t + 7)) {
                // last warp of this CTA for step t: proven publish tail
                __threadfence();
                asm volatile("red.global.gpu.add.u32 [%0], %1;"
                             :: "l"(&g_cnt), "r"(1u) : "memory");
            }
            // out store after publish: off the critical path
            __stcs(out + (size_t)t * HDIM + outIdx, hn);
        }
        target += NCTA;
    }
}

extern "C" void kernel_launch(void* const* d_in, const int* in_sizes, int n_in,
                              void* d_out, int out_size) {
    const float* x    = (const float*)d_in[0];
    const float* W_ih = (const float*)d_in[1];
    const float* W_hh = (const float*)d_in[2];
    const float* b_ih = (const float*)d_in[3];
    const float* b_hh = (const float*)d_in[4];
    float* out = (float*)d_out;
    const int N = out_size / HDIM;

    lstm_init_kernel<<<1, 32>>>();
    lstm_kernel<<<NCTA, TPB>>>(x, W_ih, W_hh, b_ih, b_hh, out, N);
}

// round 11
// speedup vs baseline: 1.3636x; 1.3636x over previous
#include <cuda_runtime.h>
#include <cstdint>

// ---------------------------------------------------------------------------
// Sequential LSTM rollout, N=10000 steps, H=1024.
// EXACT R7 protocol (best: 18.6ms) + fast tanh (isolated R9 win):
// 128 persistent CTAs x 256 threads, W_hh in registers (f32x2 pairs).
// Publish: lanes<8 st.cg h -> __syncwarp -> lane0 __threadfence ->
//          red.global.add g_cnt,1  (aggregate counter, no per-CTA flags)
// Observe: ONE lane per CTA polls ld.acquire.gpu g_cnt >= 128*t, then relays
//          through shared memory (st.release.cta / ld.acquire.cta spin).
// Output store AFTER the release so the fence never drains the DRAM write.
// Counter requires ALL CTAs -> run-ahead bounded to 1 step -> parity
// double-buffered g_hbuf / sh_part safe with ONE __syncthreads per step.
// R11 change: both library tanhf calls -> expf-based tanh_fast (~40cyc MUFU
// path vs ~200cyc library call, both sit on the global critical path).
// CTA b owns h[8b..8b+8) and gate rows {g*1024 + 8b + j}.
// Warp w owns k in [128w,128w+128).
// ---------------------------------------------------------------------------

#define HDIM  1024
#define NCTA  128
#define TPB   256
#define NWARP 8
#define WPT   64           // f32x2 weight pairs per thread (=128 k floats)

typedef unsigned long long ull;

__device__ __align__(16) float g_hbuf[2][HDIM];
__device__ unsigned            g_cnt;

__device__ __forceinline__ ull ffma2(ull a, ull b, ull c) {
    ull d;
    asm("fma.rn.f32x2 %0, %1, %2, %3;" : "=l"(d) : "l"(a), "l"(b), "l"(c));
    return d;
}
__device__ __forceinline__ ull fadd2(ull a, ull b) {
    ull d;
    asm("add.rn.f32x2 %0, %1, %2;" : "=l"(d) : "l"(a), "l"(b));
    return d;
}
__device__ __forceinline__ float pairsum(ull a) {
    float lo = __uint_as_float((unsigned)(a & 0xffffffffull));
    float hi = __uint_as_float((unsigned)(a >> 32));
    return lo + hi;
}
__device__ __forceinline__ float sigf(float x) {
    return 1.0f / (1.0f + __expf(-x));
}
// fast, accurate tanh: (1-e)/(1+e), e = exp(-2x); clamp avoids inf/inf NaN
__device__ __forceinline__ float tanh_fast(float x) {
    x = fminf(15.0f, fmaxf(-15.0f, x));
    float e = __expf(-2.0f * x);
    return (1.0f - e) / (1.0f + e);
}
__device__ __forceinline__ unsigned ld_acq_gpu(const unsigned* p) {
    unsigned v;
    asm volatile("ld.acquire.gpu.u32 %0, [%1];" : "=r"(v) : "l"(p));
    return v;
}
__device__ __forceinline__ uint32_t smem_u32(const void* p) {
    uint32_t a;
    asm("{ .reg .u64 t; cvta.to.shared.u64 t, %1; cvt.u32.u64 %0, t; }"
        : "=r"(a) : "l"(p));
    return a;
}

__global__ void lstm_init_kernel() {
    if (threadIdx.x == 0) g_cnt = 0u;
}

__global__ void __launch_bounds__(TPB) lstm_kernel(
    const float* __restrict__ x,      // [1024]
    const float* __restrict__ W_ih,   // [4096,1024] row-major
    const float* __restrict__ W_hh,   // [4096,1024] row-major
    const float* __restrict__ b_ih,   // [4096]
    const float* __restrict__ b_hh,   // [4096]
    float* __restrict__ out,          // [N,1024]
    int N)
{
    __shared__ float    sh_h[HDIM];        // warp w owns [128w,128w+128): private
    __shared__ float    sh_part[2][TPB];   // parity-double-buffered partials
    __shared__ unsigned sh_step;           // monotonic step relay

    const int tid = threadIdx.x;
    const int w   = tid >> 5;
    const int l   = tid & 31;
    const int cta = blockIdx.x;
    const int gt  = l >> 3;                // gate 0..3 (i,f,g,o)
    const int jj  = l & 7;                 // local h index 0..7
    const int rowG = gt * HDIM + cta * 8 + jj;
    const uint32_t stepAddr = smem_u32(&sh_step);

    if (tid == 0) sh_step = 0u;

    // ---- stage x into shared (reuse sh_h) ----
    ((float4*)sh_h)[tid] = ((const float4*)x)[tid];
    __syncthreads();

    // ---- prologue: x_gates = x @ W_ih^T + b_ih + b_hh for this CTA's rows ----
    float xg = 0.f;
    {
        const ull* wp = (const ull*)W_ih + (size_t)rowG * (HDIM / 2) + w * WPT;
        const ull* hp = (const ull*)sh_h + w * WPT;
        ull a0 = 0, a1 = 0, a2 = 0, a3 = 0;
        #pragma unroll
        for (int i = 0; i < WPT; i += 4) {
            a0 = ffma2(wp[i + 0], hp[i + 0], a0);
            a1 = ffma2(wp[i + 1], hp[i + 1], a1);
            a2 = ffma2(wp[i + 2], hp[i + 2], a2);
            a3 = ffma2(wp[i + 3], hp[i + 3], a3);
        }
        a0 = fadd2(a0, a1); a2 = fadd2(a2, a3); a0 = fadd2(a0, a2);
        sh_part[0][w * 32 + l] = pairsum(a0);
        __syncthreads();
        if (w == 0) {
            float s = 0.f;
            #pragma unroll
            for (int ww = 0; ww < NWARP; ww++) s += sh_part[0][ww * 32 + l];
            xg = s + b_ih[rowG] + b_hh[rowG];
        }
        __syncthreads();
    }

    // ---- preload W_hh slice into registers ----
    ull wreg[WPT];
    {
        const ull* wp = (const ull*)W_hh + (size_t)rowG * (HDIM / 2) + w * WPT;
        #pragma unroll
        for (int i = 0; i < WPT; i++) wreg[i] = wp[i];
    }

    // ---- recurrence: ONE __syncthreads per step ----
    float c = 0.f;
    unsigned target = 0u;                  // = 128*t

    for (int t = 0; t < N; ++t) {
        float dot = 0.f;
        if (t > 0) {
            const int p = (t - 1) & 1;
            const unsigned tt = (unsigned)t;

            if (w == 0) {
                if (l == 0) {
                    // single poller per CTA on the aggregate counter
                    while ((int)(ld_acq_gpu(&g_cnt) - target) < 0) { }
                    asm volatile("st.release.cta.shared.u32 [%0], %1;"
                                 :: "r"(stepAddr), "r"(tt) : "memory");
                }
                __syncwarp();
            } else {
                // local smem spin: zero L2 traffic
                unsigned v;
                do {
                    asm volatile("ld.acquire.cta.shared.u32 %0, [%1];"
                                 : "=r"(v) : "r"(stepAddr) : "memory");
                } while ((int)(v - tt) < 0);
            }

            // stage this warp's k-slice into its private smem region
            float4 hv = __ldcg((const float4*)(g_hbuf[p] + w * 128) + l);
            *((float4*)(sh_h + w * 128) + l) = hv;
            __syncwarp();

            const ull* hp = (const ull*)(sh_h + w * 128);
            ull c0 = 0, c1 = 0, c2 = 0, c3 = 0;
            #pragma unroll
            for (int i = 0; i < WPT; i += 4) {
                c0 = ffma2(wreg[i + 0], hp[i + 0], c0);
                c1 = ffma2(wreg[i + 1], hp[i + 1], c1);
                c2 = ffma2(wreg[i + 2], hp[i + 2], c2);
                c3 = ffma2(wreg[i + 3], hp[i + 3], c3);
            }
            c0 = fadd2(c0, c1); c2 = fadd2(c2, c3); c0 = fadd2(c0, c2);
            dot = pairsum(c0);
        }
        sh_part[t & 1][w * 32 + l] = dot;
        __syncthreads();

        if (w == 0) {
            float s = 0.f;
            #pragma unroll
            for (int ww = 0; ww < NWARP; ww++) s += sh_part[t & 1][ww * 32 + l];
            // activation on ALL 32 lanes (parallel MUFU), then gather
            float val = xg + s;
            float act = (gt == 2) ? tanh_fast(val) : sigf(val);
            float a_f = __shfl_sync(0xffffffffu, act, l + 8);
            float a_g = __shfl_sync(0xffffffffu, act, l + 16);
            float a_o = __shfl_sync(0xffffffffu, act, l + 24);
            float hn = 0.f;
            if (l < 8) {
                c  = a_f * c + act * a_g;       // act=i, a_f=f, a_g=g
                hn = a_o * tanh_fast(c);
                __stcg(&g_hbuf[t & 1][cta * 8 + l], hn);
            }
            __syncwarp();
            if (l == 0) {
                __threadfence();
                asm volatile("red.global.gpu.add.u32 [%0], %1;"
                             :: "l"(&g_cnt), "r"(1u) : "memory");
            }
            // out store AFTER release: fence never drains the DRAM write
            if (l < 8)
                __stcs(out + (size_t)t * HDIM + cta * 8 + l, hn);
        }
        target += NCTA;
        // no trailing barrier: sh_part for step t+1 has opposite parity; the
        // global counter requires ALL CTAs, bounding cross-CTA skew to 1 step.
    }
}

extern "C" void kernel_launch(void* const* d_in, const int* in_sizes, int n_in,
                              void* d_out, int out_size) {
    const float* x    = (const float*)d_in[0];
    const float* W_ih = (const float*)d_in[1];
    const float* W_hh = (const float*)d_in[2];
    const float* b_ih = (const float*)d_in[3];
    const float* b_hh = (const float*)d_in[4];
    float* out = (float*)d_out;
    const int N = out_size / HDIM;

    lstm_init_kernel<<<1, 32>>>();
    lstm_kernel<<<NCTA, TPB>>>(x, W_ih, W_hh, b_ih, b_hh, out, N);
}